// round 17
// baseline (speedup 1.0000x reference)
#include <cuda_runtime.h>
#include <cuda_bf16.h>
#include <cstdint>

#define NN   100000
#define NE   800000
#define IND  128
#define HID  256
#define OUTD 40
#define NB1  98   // blocks in persistent CSR kernel (< 148 SMs => co-resident)

// ---------------- scratch (static __device__ per harness rules) ----------------
__device__ int   g_cnt[NN];
__device__ int   g_rowptr[NN + 1];
__device__ int   g_cursor[NN];
__device__ int   g_col[NE];
__device__ float g_dinv[NN];
__device__ int   g_bsum[NB1];
__device__ int   g_arr1, g_arr2, g_arr3;
__device__ __nv_bfloat16 g_xah[(size_t)NN * IND];   // aggregated input, bf16 hi
__device__ __nv_bfloat16 g_xal[(size_t)NN * IND];   // aggregated input, bf16 lo
__device__ __nv_bfloat16 g_w1th[(size_t)HID * IND]; // W1^T [n][k] bf16 hi
__device__ __nv_bfloat16 g_w1tl[(size_t)HID * IND]; // W1^T [n][k] bf16 lo
__device__ __nv_bfloat16 g_w2th[(size_t)OUTD * HID]; // W2^T [n][k] bf16 hi
__device__ __nv_bfloat16 g_w2tl[(size_t)OUTD * HID]; // W2^T [n][k] bf16 lo
__device__ float g_h2t[(size_t)NN * OUTD]; // (a1@W2)*dinv[row]

// ---------------- fused init: zero counters + W1/W2 transpose-split ----------
__global__ __launch_bounds__(256) void k_init(const float* __restrict__ W1,
                                              const float* __restrict__ W2) {
    int i = blockIdx.x * 256 + threadIdx.x;
    if (i < NN) g_cnt[i] = 0;
    if (i == 0) { g_arr1 = 0; g_arr2 = 0; g_arr3 = 0; }
    if (i < HID * IND) {                        // 32768: W1 transpose+split
        int n = i & 255, k = i >> 8;
        float v = W1[(size_t)k * HID + n];
        __nv_bfloat16 h = __float2bfloat16(v);
        g_w1th[(size_t)n * IND + k] = h;
        g_w1tl[(size_t)n * IND + k] = __float2bfloat16(v - __bfloat162float(h));
    }
    if (i < OUTD * HID) {                       // 10240: W2 transpose+split
        int k = i & 255, n = i >> 8;
        float v = W2[(size_t)k * OUTD + n];
        __nv_bfloat16 h = __float2bfloat16(v);
        g_w2th[(size_t)n * HID + k] = h;
        g_w2tl[(size_t)n * HID + k] = __float2bfloat16(v - __bfloat162float(h));
    }
}

// ---------------- persistent CSR build: count -> scan -> fill ----------------
__global__ __launch_bounds__(1024) void k_csr(const int* __restrict__ src,
                                              const int* __restrict__ dst) {
    const int b = blockIdx.x, t = threadIdx.x;
    const int lane = t & 31, wid = t >> 5;
    const int base = b * 1024 + t;
    const int gstride = NB1 * 1024;             // 100352

    #pragma unroll
    for (int j = 0; j < 8; j++) {
        int e = base + j * gstride;
        if (e < NE) atomicAdd(&g_cnt[__ldg(dst + e)], 1);
    }
    if (t == 0) {
        __threadfence();
        atomicAdd(&g_arr1, 1);
        while (atomicAdd(&g_arr1, 0) < NB1) { }
    }
    __syncthreads();

    const int i = base;
    int c = (i < NN) ? g_cnt[i] : 0;
    int v = c;
    #pragma unroll
    for (int d = 1; d < 32; d <<= 1) {
        int tt = __shfl_up_sync(0xffffffffu, v, d);
        if (lane >= d) v += tt;
    }
    __shared__ int ws[32];
    if (lane == 31) ws[wid] = v;
    __syncthreads();
    if (wid == 0) {
        int w = ws[lane];
        #pragma unroll
        for (int d = 1; d < 32; d <<= 1) {
            int tt = __shfl_up_sync(0xffffffffu, w, d);
            if (lane >= d) w += tt;
        }
        ws[lane] = w;
    }
    __syncthreads();
    const int woff = wid ? ws[wid - 1] : 0;
    const int incl = v + woff;
    const int btotal = ws[31];

    if (t == 0) {
        g_bsum[b] = btotal;
        __threadfence();
        atomicAdd(&g_arr2, 1);
        while (atomicAdd(&g_arr2, 0) < NB1) { }
    }
    __syncthreads();

    __shared__ int sm[NB1];
    __shared__ int boffs;
    if (t < NB1) sm[t] = g_bsum[t];
    __syncthreads();
    if (t == 0) {
        int run = 0;
        for (int j = 0; j < b; j++) run += sm[j];
        boffs = run;
        if (b == NB1 - 1) g_rowptr[NN] = run + btotal;
    }
    __syncthreads();

    if (i < NN) {
        int excl = incl - c + boffs;
        g_rowptr[i] = excl;
        g_cursor[i] = excl;
        g_dinv[i]   = rsqrtf((float)(c + 1));  // +1 self-loop, deg >= 1
    }

    if (t == 0) {
        __threadfence();
        atomicAdd(&g_arr3, 1);
        while (atomicAdd(&g_arr3, 0) < NB1) { }
    }
    __syncthreads();

    #pragma unroll
    for (int j = 0; j < 8; j++) {
        int e = base + j * gstride;
        if (e < NE) {
            int d = __ldg(dst + e);
            int p = atomicAdd(&g_cursor[d], 1);
            g_col[p] = __ldg(src + e);
        }
    }
}

// ---------------- aggX: xa[d]=dinv[d]*(sum dinv[s]x[s] + dinv[d]x[d]), bf16 split out --
__global__ __launch_bounds__(256) void k_aggx(const float* __restrict__ x) {
    int gw = (blockIdx.x * 256 + threadIdx.x) >> 5;
    int lane = threadIdx.x & 31;
    if (gw >= NN) return;

    const float4* x4 = (const float4*)x;
    float dg = g_dinv[gw];
    float4 xs = x4[(size_t)gw * 32 + lane];
    float4 acc;
    acc.x = dg * xs.x; acc.y = dg * xs.y; acc.z = dg * xs.z; acc.w = dg * xs.w;

    int beg = g_rowptr[gw], end = g_rowptr[gw + 1];
    for (int e = beg; e < end; e++) {
        int s = g_col[e];
        float ds = g_dinv[s];
        float4 v = x4[(size_t)s * 32 + lane];
        acc.x = fmaf(ds, v.x, acc.x);
        acc.y = fmaf(ds, v.y, acc.y);
        acc.z = fmaf(ds, v.z, acc.z);
        acc.w = fmaf(ds, v.w, acc.w);
    }

    float ox = dg * acc.x, oy = dg * acc.y, oz = dg * acc.z, ow = dg * acc.w;
    __nv_bfloat16 hx = __float2bfloat16(ox), hy = __float2bfloat16(oy);
    __nv_bfloat16 hz = __float2bfloat16(oz), hw = __float2bfloat16(ow);
    __nv_bfloat162 h01, h23, l01, l23;
    h01.x = hx; h01.y = hy; h23.x = hz; h23.y = hw;
    l01.x = __float2bfloat16(ox - __bfloat162float(hx));
    l01.y = __float2bfloat16(oy - __bfloat162float(hy));
    l23.x = __float2bfloat16(oz - __bfloat162float(hz));
    l23.y = __float2bfloat16(ow - __bfloat162float(hw));
    size_t base = (size_t)gw * IND + lane * 4;
    *(__nv_bfloat162*)(g_xah + base)     = h01;
    *(__nv_bfloat162*)(g_xah + base + 2) = h23;
    *(__nv_bfloat162*)(g_xal + base)     = l01;
    *(__nv_bfloat162*)(g_xal + base + 2) = l23;
}

#define MMA16816(c, a, b)                                                       \
    asm volatile("mma.sync.aligned.m16n8k16.row.col.f32.bf16.bf16.f32 "         \
        "{%0,%1,%2,%3}, {%4,%5,%6,%7}, {%8,%9}, {%0,%1,%2,%3};"                 \
        : "+f"((c)[0]), "+f"((c)[1]), "+f"((c)[2]), "+f"((c)[3])                \
        : "r"((a)[0]), "r"((a)[1]), "r"((a)[2]), "r"((a)[3]),                   \
          "r"((b)[0]), "r"((b)[1]))

// ---------------- FUSED GEMM, 512 threads (16 warps) -------------------------
// Phase 1: 128 rows x full N=256 (two halves); warp grid 4m x 4n, tile 32x32.
// Phase 2: 16 warps = 8 row-blocks x 2 n-groups, from SMEM a1.
#define F_STRIDE 72                               // stage stride (64+8)
#define F_ARR    (128 * F_STRIDE)                 // 9216 bf16
#define F_A1STR  264                              // a1 stride (256+8)
#define F_A1H    (4 * F_ARR)                      // 36864
#define F_A1L    (F_A1H + 128 * F_A1STR)          // 70656
#define F_TOTAL  ((F_A1L + 128 * F_A1STR) * 2)    // 208896 bytes

__global__ __launch_bounds__(512, 1) void k_fused(const float* __restrict__ b1) {
    extern __shared__ __nv_bfloat16 smb[];
    __nv_bfloat16* AH  = smb;
    __nv_bfloat16* AL  = smb + F_ARR;
    __nv_bfloat16* BH  = smb + 2 * F_ARR;
    __nv_bfloat16* BL  = smb + 3 * F_ARR;
    __nv_bfloat16* A1H = smb + F_A1H;
    __nv_bfloat16* A1L = smb + F_A1L;
    __nv_bfloat16* W2H = smb;                     // aliases stage region (phase 2)
    __nv_bfloat16* W2L = smb + OUTD * F_A1STR;    // 10560

    const int tid = threadIdx.x;
    const int wid = tid >> 5, lane = tid & 31;
    const int g = lane >> 2, tg = lane & 3;
    const int wm = wid >> 2, wn = wid & 3;        // phase1 warp grid 4x4
    const int m0 = blockIdx.x * 128;

    // ================= phase 1: layer-1 GEMM, full N =================
    for (int hn = 0; hn < 2; hn++) {
        const int n0 = hn << 7;
        float acc[2][4][4];
        #pragma unroll
        for (int mi = 0; mi < 2; mi++)
            #pragma unroll
            for (int ni = 0; ni < 4; ni++)
                #pragma unroll
                for (int q = 0; q < 4; q++) acc[mi][ni][q] = 0.f;

        for (int kc = 0; kc < 2; kc++) {
            #pragma unroll
            for (int i = 0; i < 2; i++) {
                int idx = tid + i * 512;          // 0..1023
                int r = idx >> 3, c8 = idx & 7;
                size_t goff = (size_t)(m0 + r) * IND + kc * 64 + c8 * 8;
                uint4 z = make_uint4(0, 0, 0, 0);
                bool ok = (m0 + r) < NN;
                *(uint4*)(AH + r * F_STRIDE + c8 * 8) = ok ? *(const uint4*)(g_xah + goff) : z;
                *(uint4*)(AL + r * F_STRIDE + c8 * 8) = ok ? *(const uint4*)(g_xal + goff) : z;
                size_t boff = (size_t)(n0 + r) * IND + kc * 64 + c8 * 8;
                *(uint4*)(BH + r * F_STRIDE + c8 * 8) = *(const uint4*)(g_w1th + boff);
                *(uint4*)(BL + r * F_STRIDE + c8 * 8) = *(const uint4*)(g_w1tl + boff);
            }
            __syncthreads();

            #pragma unroll
            for (int ks = 0; ks < 4; ks++) {
                int k0 = ks * 16;
                uint32_t af[2][4], bh[4][2], bl[4][2];
                #pragma unroll
                for (int ni = 0; ni < 4; ni++) {
                    const __nv_bfloat16* p = BH + (wn * 32 + ni * 8 + g) * F_STRIDE + k0 + 2 * tg;
                    bh[ni][0] = *(const uint32_t*)(p);
                    bh[ni][1] = *(const uint32_t*)(p + 8);
                    const __nv_bfloat16* q = BL + (wn * 32 + ni * 8 + g) * F_STRIDE + k0 + 2 * tg;
                    bl[ni][0] = *(const uint32_t*)(q);
                    bl[ni][1] = *(const uint32_t*)(q + 8);
                }
                #pragma unroll
                for (int mi = 0; mi < 2; mi++) {
                    const __nv_bfloat16* p = AH + (wm * 32 + mi * 16 + g) * F_STRIDE + k0 + 2 * tg;
                    af[mi][0] = *(const uint32_t*)(p);
                    af[mi][1] = *(const uint32_t*)(p + 8 * F_STRIDE);
                    af[mi][2] = *(const uint32_t*)(p + 8);
                    af[mi][3] = *(const uint32_t*)(p + 8 * F_STRIDE + 8);
                }
                #pragma unroll
                for (int mi = 0; mi < 2; mi++)
                    #pragma unroll
                    for (int ni = 0; ni < 4; ni++) {
                        MMA16816(acc[mi][ni], af[mi], bh[ni]);
                        MMA16816(acc[mi][ni], af[mi], bl[ni]);
                    }
                #pragma unroll
                for (int mi = 0; mi < 2; mi++) {
                    const __nv_bfloat16* p = AL + (wm * 32 + mi * 16 + g) * F_STRIDE + k0 + 2 * tg;
                    af[mi][0] = *(const uint32_t*)(p);
                    af[mi][1] = *(const uint32_t*)(p + 8 * F_STRIDE);
                    af[mi][2] = *(const uint32_t*)(p + 8);
                    af[mi][3] = *(const uint32_t*)(p + 8 * F_STRIDE + 8);
                }
                #pragma unroll
                for (int mi = 0; mi < 2; mi++)
                    #pragma unroll
                    for (int ni = 0; ni < 4; ni++)
                        MMA16816(acc[mi][ni], af[mi], bh[ni]);
            }
            __syncthreads();
        }

        // ---- epilogue: bias + relu -> bf16 hi/lo into SMEM a1 ----
        #pragma unroll
        for (int ni = 0; ni < 4; ni++) {
            int coll = wn * 32 + ni * 8 + 2 * tg;
            float bz0 = __ldg(b1 + n0 + coll), bz1 = __ldg(b1 + n0 + coll + 1);
            #pragma unroll
            for (int mi = 0; mi < 2; mi++) {
                #pragma unroll
                for (int half = 0; half < 2; half++) {
                    int rloc = wm * 32 + mi * 16 + g + half * 8;
                    float v0 = fmaxf(acc[mi][ni][half * 2]     + bz0, 0.f);
                    float v1 = fmaxf(acc[mi][ni][half * 2 + 1] + bz1, 0.f);
                    __nv_bfloat16 h0 = __float2bfloat16(v0);
                    __nv_bfloat16 h1 = __float2bfloat16(v1);
                    __nv_bfloat162 hh, ll;
                    hh.x = h0; hh.y = h1;
                    ll.x = __float2bfloat16(v0 - __bfloat162float(h0));
                    ll.y = __float2bfloat16(v1 - __bfloat162float(h1));
                    int off = rloc * F_A1STR + n0 + coll;
                    *(__nv_bfloat162*)(A1H + off) = hh;
                    *(__nv_bfloat162*)(A1L + off) = ll;
                }
            }
        }
        __syncthreads();
    }

    // ================= phase 2: layer-2 GEMM from SMEM =================
    #pragma unroll
    for (int i = 0; i < 3; i++) {
        int idx = tid + i * 512;                 // 0..1535, need 0..1279
        if (idx < 1280) {
            int r = idx >> 5, c8 = idx & 31;
            size_t goff = (size_t)r * HID + c8 * 8;
            *(uint4*)(W2H + r * F_A1STR + c8 * 8) = *(const uint4*)(g_w2th + goff);
            *(uint4*)(W2L + r * F_A1STR + c8 * 8) = *(const uint4*)(g_w2tl + goff);
        }
    }
    __syncthreads();

    // 16 warps = 8 row-blocks (rw) x 2 n-groups (grp): grp0 -> ni 0..2, grp1 -> ni 3..4
    const int rw = wid & 7, grp = wid >> 3;
    const int nbase = grp ? 3 : 0;
    const int ncnt  = grp ? 2 : 3;

    float acc2[3][4];
    #pragma unroll
    for (int ni = 0; ni < 3; ni++)
        #pragma unroll
        for (int q = 0; q < 4; q++) acc2[ni][q] = 0.f;

    #pragma unroll
    for (int ks = 0; ks < 16; ks++) {
        int k0 = ks * 16;
        uint32_t afh[4], afl[4];
        {
            const __nv_bfloat16* p = A1H + (rw * 16 + g) * F_A1STR + k0 + 2 * tg;
            afh[0] = *(const uint32_t*)(p);
            afh[1] = *(const uint32_t*)(p + 8 * F_A1STR);
            afh[2] = *(const uint32_t*)(p + 8);
            afh[3] = *(const uint32_t*)(p + 8 * F_A1STR + 8);
            const __nv_bfloat16* q = A1L + (rw * 16 + g) * F_A1STR + k0 + 2 * tg;
            afl[0] = *(const uint32_t*)(q);
            afl[1] = *(const uint32_t*)(q + 8 * F_A1STR);
            afl[2] = *(const uint32_t*)(q + 8);
            afl[3] = *(const uint32_t*)(q + 8 * F_A1STR + 8);
        }
        #pragma unroll
        for (int ni = 0; ni < 3; ni++) {
            if (ni < ncnt) {
                uint32_t bh[2], bl[2];
                const __nv_bfloat16* p = W2H + ((nbase + ni) * 8 + g) * F_A1STR + k0 + 2 * tg;
                bh[0] = *(const uint32_t*)(p);
                bh[1] = *(const uint32_t*)(p + 8);
                const __nv_bfloat16* q = W2L + ((nbase + ni) * 8 + g) * F_A1STR + k0 + 2 * tg;
                bl[0] = *(const uint32_t*)(q);
                bl[1] = *(const uint32_t*)(q + 8);
                MMA16816(acc2[ni], afh, bh);
                MMA16816(acc2[ni], afh, bl);
                MMA16816(acc2[ni], afl, bh);
            }
        }
    }

    #pragma unroll
    for (int half = 0; half < 2; half++) {
        int row = m0 + rw * 16 + g + half * 8;
        if (row < NN) {
            float di = g_dinv[row];
            #pragma unroll
            for (int ni = 0; ni < 3; ni++) {
                if (ni < ncnt) {
                    float2 o;
                    o.x = acc2[ni][half * 2]     * di;
                    o.y = acc2[ni][half * 2 + 1] * di;
                    *(float2*)(g_h2t + (size_t)row * OUTD + (nbase + ni) * 8 + 2 * tg) = o;
                }
            }
        }
    }
}

// ---------------- agg2 + bias + log_softmax ----------------
__global__ __launch_bounds__(256) void k_agg2(const float* __restrict__ b2,
                                              float* __restrict__ out) {
    int gw = (blockIdx.x * 256 + threadIdx.x) >> 5;
    int lane = threadIdx.x & 31;
    if (gw >= NN) return;
    bool hi = lane < 8;

    const float* self = g_h2t + (size_t)gw * OUTD;
    float a0 = self[lane];
    float a1v = hi ? self[32 + lane] : 0.f;

    int beg = g_rowptr[gw], end = g_rowptr[gw + 1];
    for (int e = beg; e < end; e++) {
        int s = g_col[e];
        const float* p = g_h2t + (size_t)s * OUTD;
        a0 += p[lane];
        if (hi) a1v += p[32 + lane];
    }

    float di = g_dinv[gw];
    float z0 = fmaf(di, a0, b2[lane]);
    float z1 = hi ? fmaf(di, a1v, b2[32 + lane]) : -3.4e38f;

    float mx = fmaxf(z0, z1);
    #pragma unroll
    for (int d = 16; d; d >>= 1) mx = fmaxf(mx, __shfl_xor_sync(0xffffffffu, mx, d));
    float s0 = expf(z0 - mx) + (hi ? expf(z1 - mx) : 0.f);
    #pragma unroll
    for (int d = 16; d; d >>= 1) s0 += __shfl_xor_sync(0xffffffffu, s0, d);
    float lse = mx + logf(s0);

    out[(size_t)gw * OUTD + lane] = z0 - lse;
    if (hi) out[(size_t)gw * OUTD + 32 + lane] = z1 - lse;
}

// ---------------- launch ----------------
extern "C" void kernel_launch(void* const* d_in, const int* in_sizes, int n_in,
                              void* d_out, int out_size) {
    const float* x  = (const float*)d_in[0];
    const int*   ei = (const int*)d_in[1];
    const float* W1 = (const float*)d_in[2];
    const float* b1 = (const float*)d_in[3];
    const float* W2 = (const float*)d_in[4];
    const float* b2 = (const float*)d_in[5];
    const int* src = ei;
    const int* dst = ei + NE;
    float* out = (float*)d_out;

    // Idempotent, capture-safe (not a stream op); no static guard per harness rules.
    cudaFuncSetAttribute(k_fused, cudaFuncAttributeMaxDynamicSharedMemorySize, F_TOTAL);

    k_init<<<(NN + 255) / 256, 256>>>(W1, W2);
    k_csr<<<NB1, 1024>>>(src, dst);
    k_aggx<<<(NN * 32 + 255) / 256, 256>>>(x);
    k_fused<<<(NN + 127) / 128, 512, F_TOTAL>>>(b1);
    k_agg2<<<(NN * 32 + 255) / 256, 256>>>(b2, out);
}